// round 15
// baseline (speedup 1.0000x reference)
#include <cuda_runtime.h>
#include <cuda_bf16.h>
#include <cuda_fp16.h>
#include <math.h>
#include <float.h>
#include <stdint.h>

// ---------------------------------------------------------------------------
// Problem constants
// ---------------------------------------------------------------------------
#define NTOK   4096
#define DMODEL 1024
#define DFF    4096
#define DN     128
#define NHEADS 8
#define HDIM   16
#define TOPK   32
#define NKROW  (NTOK * TOPK)   // 131072

// ---------------------------------------------------------------------------
// Scratch
// ---------------------------------------------------------------------------
__device__ float g_xn[NTOK * DMODEL];
__device__ float g_h[NTOK * DMODEL];
__device__ float g_scores[(size_t)NTOK * DFF];
__device__ int   g_idx[NTOK * TOPK];
__device__ float g_qkv[(size_t)NKROW * 3 * DN];
__device__ float g_ao[(size_t)NKROW * DN];
__device__ float g_atd[(size_t)NKROW * DN];
__device__ float g_g1[(size_t)NKROW * 64];
__device__ float g_base[NKROW];
__device__ float g_wp1pad[DN * DN];
__device__ float g_wp1bpad[DN];

// ---------------------------------------------------------------------------
// Helpers
// ---------------------------------------------------------------------------
__device__ __forceinline__ float gelu_f(float v) {
    return 0.5f * v * (1.0f + erff(v * 0.70710678118654752f));
}
__device__ __forceinline__ float warp_sum(float v) {
    #pragma unroll
    for (int o = 16; o > 0; o >>= 1) v += __shfl_xor_sync(0xffffffffu, v, o);
    return v;
}
__device__ __forceinline__ float warp_max(float v) {
    #pragma unroll
    for (int o = 16; o > 0; o >>= 1) v = fmaxf(v, __shfl_xor_sync(0xffffffffu, v, o));
    return v;
}
__device__ __forceinline__ float tf32_rna(float x) {
    float r;
    asm("cvt.rna.tf32.f32 %0, %1;" : "=f"(r) : "f"(x));
    return r;
}

// m16n8k8 tf32 mma
__device__ __forceinline__ void mma8(float* c, const uint32_t a[4], const uint32_t b[2]) {
    asm volatile(
        "mma.sync.aligned.m16n8k8.row.col.f32.tf32.tf32.f32 "
        "{%0,%1,%2,%3}, {%4,%5,%6,%7}, {%8,%9}, {%0,%1,%2,%3};"
        : "+f"(c[0]), "+f"(c[1]), "+f"(c[2]), "+f"(c[3])
        : "r"(a[0]), "r"(a[1]), "r"(a[2]), "r"(a[3]), "r"(b[0]), "r"(b[1]));
}
// m16n8k16 fp16 mma (fp32 accumulate)
__device__ __forceinline__ void mma16h(float* c, const uint32_t a[4], const uint32_t b[2]) {
    asm volatile(
        "mma.sync.aligned.m16n8k16.row.col.f32.f16.f16.f32 "
        "{%0,%1,%2,%3}, {%4,%5,%6,%7}, {%8,%9}, {%0,%1,%2,%3};"
        : "+f"(c[0]), "+f"(c[1]), "+f"(c[2]), "+f"(c[3])
        : "r"(a[0]), "r"(a[1]), "r"(a[2]), "r"(a[3]), "r"(b[0]), "r"(b[1]));
}

#define GS 36   // tf32 smem row stride in floats (32 data + 4 pad)

__device__ __forceinline__ void frag_a(uint32_t a[4], const float* S, int row, int kc, int lane) {
    int r = lane >> 2, c = lane & 3;
    a[0] = __float_as_uint(S[(row + r) * GS + kc + c]);
    a[1] = __float_as_uint(S[(row + r + 8) * GS + kc + c]);
    a[2] = __float_as_uint(S[(row + r) * GS + kc + c + 4]);
    a[3] = __float_as_uint(S[(row + r + 8) * GS + kc + c + 4]);
}
__device__ __forceinline__ void frag_b(uint32_t b[2], const float* S, int col, int kc, int lane) {
    int n = lane >> 2, c = lane & 3;
    b[0] = __float_as_uint(S[(col + n) * GS + kc + c]);
    b[1] = __float_as_uint(S[(col + n) * GS + kc + c + 4]);
}

// ---------------------------------------------------------------------------
// LayerNorm
// ---------------------------------------------------------------------------
__global__ void ln_kernel(const float* __restrict__ x,
                          const float* __restrict__ g,
                          const float* __restrict__ b,
                          float* __restrict__ xn) {
    __shared__ float red[16];
    __shared__ float s_mu, s_r;
    int n = blockIdx.x, tid = threadIdx.x, w = tid >> 5, lane = tid & 31;
    float4 v = ((const float4*)(x + (size_t)n * DMODEL))[tid];
    float s = v.x + v.y + v.z + v.w;
    float q = v.x * v.x + v.y * v.y + v.z * v.z + v.w * v.w;
    s = warp_sum(s); q = warp_sum(q);
    if (lane == 0) { red[w] = s; red[8 + w] = q; }
    __syncthreads();
    if (tid == 0) {
        float ts = 0.f, tq = 0.f;
        for (int i = 0; i < 8; i++) { ts += red[i]; tq += red[8 + i]; }
        float mu = ts * (1.0f / DMODEL);
        float var = tq * (1.0f / DMODEL) - mu * mu;
        s_mu = mu; s_r = rsqrtf(var + 1e-5f);
    }
    __syncthreads();
    float mu = s_mu, r = s_r;
    float4 gv = ((const float4*)g)[tid];
    float4 bv = ((const float4*)b)[tid];
    float4 o;
    o.x = (v.x - mu) * r * gv.x + bv.x;
    o.y = (v.y - mu) * r * gv.y + bv.y;
    o.z = (v.z - mu) * r * gv.z + bv.z;
    o.w = (v.w - mu) * r * gv.w + bv.w;
    ((float4*)(xn + (size_t)n * DMODEL))[tid] = o;
}

// ---------------------------------------------------------------------------
// 3xTF32 GEMM — double-buffered with staging INTERLEAVED into the MMA loop:
// per kc-iteration, MMA(kc of cur) then store slice kc of next chunk.
// 256 thr, 8 warps, 64x32 warp tiles, CTA 128x128.
// ---------------------------------------------------------------------------
#define BUFSZ3 (4 * 128 * GS)
#define SMEM3DB (2 * BUFSZ3 * 4)

template <int ACT>
__global__ void __launch_bounds__(256, 1)
mma_gemm3(const float* __restrict__ A,
          const float* __restrict__ B,
          float* __restrict__ C,
          int K, int ldc, int kchunks) {
    extern __shared__ float sm[];

    int tid = threadIdx.x, lane = tid & 31, wid = tid >> 5;
    int m0 = blockIdx.y * 128, n0 = blockIdx.x * 128;
    int mw = (wid >> 2) * 64, nw = (wid & 3) * 32;

    int r0 = tid >> 3, c4 = tid & 7;
    const float* Ap[4];
    const float* Bp[4];
    #pragma unroll
    for (int i = 0; i < 4; i++) {
        int r = r0 + 32 * i;
        Ap[i] = A + (size_t)(m0 + r) * K + c4 * 4;
        Bp[i] = B + (size_t)(n0 + r) * K + c4 * 4;
    }

    float acc[4][4][4];
    #pragma unroll
    for (int mt = 0; mt < 4; mt++)
        #pragma unroll
        for (int nt = 0; nt < 4; nt++)
            #pragma unroll
            for (int e = 0; e < 4; e++) acc[mt][nt][e] = 0.f;

    float4 pa[4], pb[4];
    #pragma unroll
    for (int i = 0; i < 4; i++) { pa[i] = *(const float4*)Ap[i]; pb[i] = *(const float4*)Bp[i]; }

    // stage slice i (of 4) of the prefetched chunk into buffer buf
    auto stage_i = [&](int buf, int i) {
        float* Ah = sm + buf * BUFSZ3;
        float* Al = Ah + 128 * GS;
        float* Bh = Ah + 2 * 128 * GS;
        float* Bl = Bh + 128 * GS;
        int r = r0 + 32 * i;
        float4 av = pa[i], bv = pb[i];
        float4 ah, bh, al, bl;
        ah.x = tf32_rna(av.x); ah.y = tf32_rna(av.y);
        ah.z = tf32_rna(av.z); ah.w = tf32_rna(av.w);
        bh.x = tf32_rna(bv.x); bh.y = tf32_rna(bv.y);
        bh.z = tf32_rna(bv.z); bh.w = tf32_rna(bv.w);
        al.x = tf32_rna(av.x - ah.x); al.y = tf32_rna(av.y - ah.y);
        al.z = tf32_rna(av.z - ah.z); al.w = tf32_rna(av.w - ah.w);
        bl.x = tf32_rna(bv.x - bh.x); bl.y = tf32_rna(bv.y - bh.y);
        bl.z = tf32_rna(bv.z - bh.z); bl.w = tf32_rna(bv.w - bh.w);
        *(float4*)&Ah[r * GS + c4 * 4] = ah;
        *(float4*)&Bh[r * GS + c4 * 4] = bh;
        *(float4*)&Al[r * GS + c4 * 4] = al;
        *(float4*)&Bl[r * GS + c4 * 4] = bl;
    };

    #pragma unroll
    for (int i = 0; i < 4; i++) stage_i(0, i);
    __syncthreads();

    for (int ch = 0; ch < kchunks; ch++) {
        int cur = ch & 1;
        bool more = (ch + 1 < kchunks);
        if (more) {
            int off = (ch + 1) * 32;
            #pragma unroll
            for (int i = 0; i < 4; i++) {
                pa[i] = *(const float4*)(Ap[i] + off);
                pb[i] = *(const float4*)(Bp[i] + off);
            }
        }

        const float* Ah = sm + cur * BUFSZ3;
        const float* Al = Ah + 128 * GS;
        const float* Bh = Ah + 2 * 128 * GS;
        const float* Bl = Bh + 128 * GS;

        #pragma unroll
        for (int kidx = 0; kidx < 4; kidx++) {
            int kc = kidx * 8;
            uint32_t af[4][4], bf[4][2];
            #pragma unroll
            for (int mt = 0; mt < 4; mt++) frag_a(af[mt], Ah, mw + mt * 16, kc, lane);
            #pragma unroll
            for (int nt = 0; nt < 4; nt++) frag_b(bf[nt], Bh, nw + nt * 8, kc, lane);
            #pragma unroll
            for (int mt = 0; mt < 4; mt++)
                #pragma unroll
                for (int nt = 0; nt < 4; nt++)
                    mma8(acc[mt][nt], af[mt], bf[nt]);

            uint32_t blf[4][2];
            #pragma unroll
            for (int nt = 0; nt < 4; nt++) frag_b(blf[nt], Bl, nw + nt * 8, kc, lane);
            #pragma unroll
            for (int mt = 0; mt < 4; mt++)
                #pragma unroll
                for (int nt = 0; nt < 4; nt++)
                    mma8(acc[mt][nt], af[mt], blf[nt]);

            uint32_t alf[4][4];
            #pragma unroll
            for (int mt = 0; mt < 4; mt++) frag_a(alf[mt], Al, mw + mt * 16, kc, lane);
            #pragma unroll
            for (int mt = 0; mt < 4; mt++)
                #pragma unroll
                for (int nt = 0; nt < 4; nt++)
                    mma8(acc[mt][nt], alf[mt], bf[nt]);

            // interleave: store slice kidx of the NEXT chunk into the other buffer
            if (more) stage_i(cur ^ 1, kidx);
        }
        __syncthreads();
    }

    // epilogue
    int r = lane >> 2, c2 = (lane & 3) * 2;
    #pragma unroll
    for (int mt = 0; mt < 4; mt++) {
        #pragma unroll
        for (int nt = 0; nt < 4; nt++) {
            int row = m0 + mw + mt * 16 + r;
            int col = n0 + nw + nt * 8 + c2;
            float v0 = acc[mt][nt][0];
            float v1 = acc[mt][nt][1];
            float v2 = acc[mt][nt][2];
            float v3 = acc[mt][nt][3];
            if (ACT == 1) { v0 = gelu_f(v0); v1 = gelu_f(v1); v2 = gelu_f(v2); v3 = gelu_f(v3); }
            float2 lo; lo.x = v0; lo.y = v1;
            float2 hi; hi.x = v2; hi.y = v3;
            *(float2*)&C[(size_t)row * ldc + col] = lo;
            *(float2*)&C[(size_t)(row + 8) * ldc + col] = hi;
        }
    }
}

// ---------------------------------------------------------------------------
// FP16 1-pass GEMM (gate path only) — now double-buffered + interleaved staging.
// 256 thr, 8 warps, 64x32 warp tiles, CTA 128x128, K chunks of 32.
// ---------------------------------------------------------------------------
#define GSH 40
#define HBUF (2 * 128 * GSH)                 // halfs per buffer (A then B)
#define H16SMEM (2 * HBUF * 2)               // bytes

__device__ __forceinline__ void frag_a_h(uint32_t a[4], const __half* S, int row, int kc, int lane) {
    int r = lane >> 2, c = (lane & 3) * 2;
    a[0] = *(const uint32_t*)&S[(row + r) * GSH + kc + c];
    a[1] = *(const uint32_t*)&S[(row + r + 8) * GSH + kc + c];
    a[2] = *(const uint32_t*)&S[(row + r) * GSH + kc + c + 8];
    a[3] = *(const uint32_t*)&S[(row + r + 8) * GSH + kc + c + 8];
}
__device__ __forceinline__ void frag_b_h(uint32_t b[2], const __half* S, int col, int kc, int lane) {
    int n = lane >> 2, c = (lane & 3) * 2;
    b[0] = *(const uint32_t*)&S[(col + n) * GSH + kc + c];
    b[1] = *(const uint32_t*)&S[(col + n) * GSH + kc + c + 8];
}

template <int ACT>
__global__ void __launch_bounds__(256, 1)
mma_gemm_h16(const float* __restrict__ A,
             const float* __restrict__ B,
             const float* __restrict__ bias,
             const int* __restrict__ rowidx,
             float* __restrict__ C,
             int K, int ldc, int kchunks, int nvalid) {
    extern __shared__ __half smh[];

    int tid = threadIdx.x, lane = tid & 31, wid = tid >> 5;
    int m0 = blockIdx.y * 128, n0 = blockIdx.x * 128;
    int mw = (wid >> 2) * 64, nw = (wid & 3) * 32;

    int r0 = tid >> 3, c4 = tid & 7;
    const float* Ap[4];
    const float* Bp[4];
    #pragma unroll
    for (int i = 0; i < 4; i++) {
        int r = r0 + 32 * i;
        int ar = rowidx ? rowidx[m0 + r] : (m0 + r);
        Ap[i] = A + (size_t)ar * K + c4 * 4;
        Bp[i] = B + (size_t)(n0 + r) * K + c4 * 4;
    }

    float acc[4][4][4];
    #pragma unroll
    for (int mt = 0; mt < 4; mt++)
        #pragma unroll
        for (int nt = 0; nt < 4; nt++)
            #pragma unroll
            for (int e = 0; e < 4; e++) acc[mt][nt][e] = 0.f;

    float4 pa[4], pb[4];
    #pragma unroll
    for (int i = 0; i < 4; i++) { pa[i] = *(const float4*)Ap[i]; pb[i] = *(const float4*)Bp[i]; }

    auto stage_i = [&](int buf, int i) {
        __half* Ah = smh + buf * HBUF;
        __half* Bh = Ah + 128 * GSH;
        int r = r0 + 32 * i;
        float4 av = pa[i], bv = pb[i];
        __half2 a01 = __floats2half2_rn(av.x, av.y);
        __half2 a23 = __floats2half2_rn(av.z, av.w);
        __half2 b01 = __floats2half2_rn(bv.x, bv.y);
        __half2 b23 = __floats2half2_rn(bv.z, bv.w);
        uint2 au; au.x = *(uint32_t*)&a01; au.y = *(uint32_t*)&a23;
        uint2 bu; bu.x = *(uint32_t*)&b01; bu.y = *(uint32_t*)&b23;
        *(uint2*)&Ah[r * GSH + c4 * 4] = au;
        *(uint2*)&Bh[r * GSH + c4 * 4] = bu;
    };

    #pragma unroll
    for (int i = 0; i < 4; i++) stage_i(0, i);
    __syncthreads();

    for (int ch = 0; ch < kchunks; ch++) {
        int cur = ch & 1;
        bool more = (ch + 1 < kchunks);
        if (more) {
            int off = (ch + 1) * 32;
            #pragma unroll
            for (int i = 0; i < 4; i++) {
                pa[i] = *(const float4*)(Ap[i] + off);
                pb[i] = *(const float4*)(Bp[i] + off);
            }
        }

        const __half* Ah = smh + cur * HBUF;
        const __half* Bh = Ah + 128 * GSH;

        #pragma unroll
        for (int ks = 0; ks < 2; ks++) {
            int kc = ks * 16;
            uint32_t af[4][4], bf[4][2];
            #pragma unroll
            for (int mt = 0; mt < 4; mt++) frag_a_h(af[mt], Ah, mw + mt * 16, kc, lane);
            #pragma unroll
            for (int nt = 0; nt < 4; nt++) frag_b_h(bf[nt], Bh, nw + nt * 8, kc, lane);
            #pragma unroll
            for (int mt = 0; mt < 4; mt++)
                #pragma unroll
                for (int nt = 0; nt < 4; nt++)
                    mma16h(acc[mt][nt], af[mt], bf[nt]);

            // interleave: stage 2 slices of next chunk per k16 step
            if (more) { stage_i(cur ^ 1, ks * 2); stage_i(cur ^ 1, ks * 2 + 1); }
        }
        __syncthreads();
    }

    // epilogue
    int r = lane >> 2, c2 = (lane & 3) * 2;
    #pragma unroll
    for (int mt = 0; mt < 4; mt++) {
        #pragma unroll
        for (int nt = 0; nt < 4; nt++) {
            int row = m0 + mw + mt * 16 + r;
            int col = n0 + nw + nt * 8 + c2;
            if (col >= nvalid) continue;
            float b0 = bias ? bias[col] : 0.f;
            float b1 = bias ? bias[col + 1] : 0.f;
            float v0 = acc[mt][nt][0] + b0;
            float v1 = acc[mt][nt][1] + b1;
            float v2 = acc[mt][nt][2] + b0;
            float v3 = acc[mt][nt][3] + b1;
            if (ACT == 1) { v0 = gelu_f(v0); v1 = gelu_f(v1); v2 = gelu_f(v2); v3 = gelu_f(v3); }
            float2 lo; lo.x = v0; lo.y = v1;
            float2 hi; hi.x = v2; hi.y = v3;
            *(float2*)&C[(size_t)row * ldc + col] = lo;
            *(float2*)&C[(size_t)(row + 8) * ldc + col] = hi;
        }
    }
}

// ---------------------------------------------------------------------------
// Top-32 per row — cached per-thread argmax (proven 117-us version)
// ---------------------------------------------------------------------------
__global__ void topk_kernel(const float* __restrict__ scores,
                            int* __restrict__ idxout) {
    __shared__ float sv[DFF];
    __shared__ float swv[8];
    __shared__ int   swi[8];
    __shared__ int   sgi;
    int n = blockIdx.x, tid = threadIdx.x, w = tid >> 5, lane = tid & 31;
    const float4* s4 = (const float4*)(scores + (size_t)n * DFF);
    for (int i = tid; i < DFF / 4; i += 256)
        ((float4*)sv)[i] = s4[i];
    __syncthreads();

    float lmax = -FLT_MAX; int lidx = tid;
    #pragma unroll
    for (int t = 0; t < 16; t++) {
        int j = tid + 256 * t;
        float v = sv[j];
        if (v > lmax) { lmax = v; lidx = j; }
    }
    for (int r = 0; r < TOPK; r++) {
        float b = lmax; int bi = lidx;
        #pragma unroll
        for (int o = 16; o > 0; o >>= 1) {
            float ov = __shfl_down_sync(0xffffffffu, b, o);
            int   oi = __shfl_down_sync(0xffffffffu, bi, o);
            if (ov > b || (ov == b && oi < bi)) { b = ov; bi = oi; }
        }
        if (lane == 0) { swv[w] = b; swi[w] = bi; }
        __syncthreads();
        if (tid == 0) {
            float gb = swv[0]; int gi = swi[0];
            for (int q = 1; q < 8; q++)
                if (swv[q] > gb || (swv[q] == gb && swi[q] < gi)) { gb = swv[q]; gi = swi[q]; }
            idxout[n * TOPK + r] = gi;
            sgi = gi;
            sv[gi] = -FLT_MAX;
        }
        __syncthreads();
        int gi = sgi;
        if ((gi & 255) == tid) {
            lmax = -FLT_MAX; lidx = tid;
            #pragma unroll
            for (int t = 0; t < 16; t++) {
                int j = tid + 256 * t;
                float v = sv[j];
                if (v > lmax) { lmax = v; lidx = j; }
            }
        }
    }
}

// ---------------------------------------------------------------------------
// Pad wp1 [64,128] -> [128,128] (zeros) and wp1b [64] -> [128]
// ---------------------------------------------------------------------------
__global__ void pad_wp1_kernel(const float* __restrict__ wp1,
                               const float* __restrict__ wp1b,
                               float* __restrict__ wpad,
                               float* __restrict__ bpad) {
    int i = blockIdx.x * 256 + threadIdx.x;
    if (i < DN * DN) {
        int r = i >> 7;
        wpad[i] = (r < 64) ? wp1[i] : 0.f;
    }
    if (i < DN) bpad[i] = (i < 64) ? wp1b[i] : 0.f;
}

// ---------------------------------------------------------------------------
// token_attn: base gate + 8-head attention over k=32 neurons.
// ---------------------------------------------------------------------------
#define SQKV_STRIDE 388
#define ATTN_SMEM_FLOATS (12416 + 1024 + 1024 + 4096 + 32 + 32)

__global__ void token_attn(const float* __restrict__ x,
                           const float* __restrict__ pats,
                           const int* __restrict__ idx,
                           const float* __restrict__ qkv,
                           float* __restrict__ ao_out,
                           float* __restrict__ base_out) {
    extern __shared__ float smf[];
    float* sqkv  = smf;
    float* satt  = smf + 12416;
    float* sx    = smf + 13440;
    float* sao   = smf + 14464;
    float* sbase = smf + 18560;
    int*   skid  = (int*)(smf + 18592);

    int n = blockIdx.x, tid = threadIdx.x, w = tid >> 5, lane = tid & 31;

    if (tid < TOPK) skid[tid] = idx[n * TOPK + tid];
    ((float4*)sx)[tid] = ((const float4*)x)[(size_t)n * 256 + tid];
    __syncthreads();

    {
        const float* qn = qkv + (size_t)n * (TOPK * 3 * DN);
        for (int i = tid; i < TOPK * 3 * DN; i += 256) {
            int r = i / 384, c = i - r * 384;
            sqkv[r * SQKV_STRIDE + c] = qn[i];
        }
    }

    {
        const float4* xs = (const float4*)sx;
        #pragma unroll
        for (int r = 0; r < 4; r++) {
            int kk = w * 4 + r;
            const float4* p = (const float4*)(pats + (size_t)skid[kk] * DMODEL);
            float s = 0.f;
            #pragma unroll
            for (int j = 0; j < 8; j++) {
                int i = lane + 32 * j;
                float4 a = p[i], bq = xs[i];
                s += a.x * bq.x + a.y * bq.y + a.z * bq.z + a.w * bq.w;
            }
            s = warp_sum(s);
            if (lane == 0) sbase[kk] = gelu_f(s);
        }
    }
    __syncthreads();

    for (int h = 0; h < NHEADS; h++) {
        #pragma unroll
        for (int it = 0; it < 4; it++) {
            int e = tid + 256 * it;
            int qi = e >> 5, ki = e & 31;
            const float4* q4 = (const float4*)(sqkv + qi * SQKV_STRIDE + h * HDIM);
            const float4* k4 = (const float4*)(sqkv + ki * SQKV_STRIDE + DN + h * HDIM);
            float s = 0.f;
            #pragma unroll
            for (int j = 0; j < 4; j++) {
                float4 a = q4[j], b = k4[j];
                s += a.x * b.x + a.y * b.y + a.z * b.z + a.w * b.w;
            }
            satt[e] = s * 0.25f;
        }
        __syncthreads();
        #pragma unroll
        for (int r = 0; r < 4; r++) {
            int qi = w * 4 + r;
            float v = satt[qi * 32 + lane];
            float m = warp_max(v);
            float e2 = __expf(v - m);
            float s = warp_sum(e2);
            satt[qi * 32 + lane] = e2 / s;
        }
        __syncthreads();
        #pragma unroll
        for (int it = 0; it < 2; it++) {
            int e = tid + 256 * it;
            int qi = e >> 4, dc = e & 15;
            float s = 0.f;
            #pragma unroll
            for (int ki = 0; ki < 32; ki++)
                s = fmaf(satt[qi * 32 + ki], sqkv[ki * SQKV_STRIDE + 2 * DN + h * HDIM + dc], s);
            sao[qi * DN + h * HDIM + dc] = s;
        }
        __syncthreads();
    }

    {
        float* dst = ao_out + (size_t)n * (TOPK * DN);
        for (int i = tid; i < TOPK * DN / 4; i += 256)
            ((float4*)dst)[i] = ((const float4*)sao)[i];
        if (tid < TOPK) base_out[n * TOPK + tid] = sbase[tid];
    }
}

// ---------------------------------------------------------------------------
// token_final: gate = base * sigmoid(g1 . wp2 + b2); out = sum_k gate*dirs
// ---------------------------------------------------------------------------
__global__ void token_final(const float* __restrict__ g1,
                            const float* __restrict__ base,
                            const float* __restrict__ wp2,
                            const float* __restrict__ wp2b,
                            const int* __restrict__ idx,
                            const float* __restrict__ dirs,
                            float* __restrict__ out) {
    __shared__ float sgate[TOPK];
    __shared__ int   skid[TOPK];
    __shared__ float swp2[64];
    int n = blockIdx.x, tid = threadIdx.x, w = tid >> 5, lane = tid & 31;
    if (tid < 64) swp2[tid] = wp2[tid];
    if (tid < TOPK) skid[tid] = idx[n * TOPK + tid];
    __syncthreads();

    float b2 = wp2b[0];
    #pragma unroll
    for (int r = 0; r < 4; r++) {
        int k = w * 4 + r;
        const float* row = g1 + (size_t)(n * TOPK + k) * 64;
        float s = row[lane] * swp2[lane] + row[lane + 32] * swp2[lane + 32];
        s = warp_sum(s);
        if (lane == 0) {
            float sig = 1.0f / (1.0f + __expf(-(s + b2)));
            sgate[k] = base[n * TOPK + k] * sig;
        }
    }
    __syncthreads();

    float4 acc; acc.x = acc.y = acc.z = acc.w = 0.f;
    #pragma unroll 4
    for (int k = 0; k < TOPK; k++) {
        float g = sgate[k];
        const float4* dr = (const float4*)(dirs + (size_t)skid[k] * DMODEL);
        float4 v = dr[tid];
        acc.x = fmaf(g, v.x, acc.x);
        acc.y = fmaf(g, v.y, acc.y);
        acc.z = fmaf(g, v.z, acc.z);
        acc.w = fmaf(g, v.w, acc.w);
    }
    ((float4*)out)[(size_t)n * 256 + tid] = acc;
}

// ---------------------------------------------------------------------------
// Launch
// ---------------------------------------------------------------------------
extern "C" void kernel_launch(void* const* d_in, const int* in_sizes, int n_in,
                              void* d_out, int out_size) {
    const float* x    = (const float*)d_in[0];
    const float* pats = (const float*)d_in[1];
    const float* vecs = (const float*)d_in[2];
    const float* dirs = (const float*)d_in[3];
    const float* rw1  = (const float*)d_in[4];
    const float* rw2  = (const float*)d_in[5];
    const float* lng  = (const float*)d_in[6];
    const float* lnb  = (const float*)d_in[7];
    const float* inw  = (const float*)d_in[8];
    const float* inb  = (const float*)d_in[9];
    const float* outw = (const float*)d_in[10];
    const float* outb = (const float*)d_in[11];
    const float* wp1  = (const float*)d_in[12];
    const float* wp1b = (const float*)d_in[13];
    const float* wp2  = (const float*)d_in[14];
    const float* wp2b = (const float*)d_in[15];
    float* out = (float*)d_out;

    float *p_xn, *p_h, *p_scores, *p_qkv, *p_ao, *p_atd, *p_g1, *p_base, *p_w1p, *p_b1p;
    int *p_idx;
    cudaGetSymbolAddress((void**)&p_xn, g_xn);
    cudaGetSymbolAddress((void**)&p_h, g_h);
    cudaGetSymbolAddress((void**)&p_scores, g_scores);
    cudaGetSymbolAddress((void**)&p_idx, g_idx);
    cudaGetSymbolAddress((void**)&p_qkv, g_qkv);
    cudaGetSymbolAddress((void**)&p_ao, g_ao);
    cudaGetSymbolAddress((void**)&p_atd, g_atd);
    cudaGetSymbolAddress((void**)&p_g1, g_g1);
    cudaGetSymbolAddress((void**)&p_base, g_base);
    cudaGetSymbolAddress((void**)&p_w1p, g_wp1pad);
    cudaGetSymbolAddress((void**)&p_b1p, g_wp1bpad);

    static int attr_set = 0;
    if (!attr_set) {
        cudaFuncSetAttribute(token_attn,
                             cudaFuncAttributeMaxDynamicSharedMemorySize,
                             ATTN_SMEM_FLOATS * 4);
        cudaFuncSetAttribute(mma_gemm3<1>,
                             cudaFuncAttributeMaxDynamicSharedMemorySize, SMEM3DB);
        cudaFuncSetAttribute(mma_gemm3<0>,
                             cudaFuncAttributeMaxDynamicSharedMemorySize, SMEM3DB);
        cudaFuncSetAttribute(mma_gemm_h16<0>,
                             cudaFuncAttributeMaxDynamicSharedMemorySize, H16SMEM);
        cudaFuncSetAttribute(mma_gemm_h16<1>,
                             cudaFuncAttributeMaxDynamicSharedMemorySize, H16SMEM);
        attr_set = 1;
    }

    // 0) pad wp1 for the padded-N batched gemm
    pad_wp1_kernel<<<64, 256>>>(wp1, wp1b, p_w1p, p_b1p);

    // 1) LayerNorm
    ln_kernel<<<NTOK, 256>>>(x, lng, lnb, p_xn);

    // 2) h = gelu(xn @ rw1^T)   (3xTF32, interleaved double-buffer)
    mma_gemm3<1><<<dim3(DMODEL / 128, NTOK / 128), 256, SMEM3DB>>>(
        p_xn, rw1, p_h, DMODEL, DMODEL, DMODEL / 32);

    // 3) scores = h @ rw2^T     (3xTF32, interleaved double-buffer)
    mma_gemm3<0><<<dim3(DFF / 128, NTOK / 128), 256, SMEM3DB>>>(
        p_h, rw2, p_scores, DMODEL, DFF, DMODEL / 32);

    // 4) top-32 per token
    topk_kernel<<<NTOK, 256>>>(p_scores, p_idx);

    // 5) qkv = gather(neuron_vecs, idx) @ in_proj_w^T + b   (fp16, gate-safe)
    mma_gemm_h16<0><<<dim3((3 * DN) / 128, NKROW / 128), 256, H16SMEM>>>(
        vecs, inw, inb, p_idx, p_qkv, DN, 3 * DN, DN / 32, 3 * DN);

    // 6) per-token attention + base -> ao, base scratch
    token_attn<<<NTOK, 256, ATTN_SMEM_FLOATS * 4>>>(
        x, pats, p_idx, p_qkv, p_ao, p_base);

    // 7) attended = ao @ outw^T + outb   (fp16, batched over all (n,k) rows)
    mma_gemm_h16<0><<<dim3(1, NKROW / 128), 256, H16SMEM>>>(
        p_ao, outw, outb, nullptr, p_atd, DN, DN, DN / 32, DN);

    // 8) g1 = gelu(attended @ wp1^T + b1)  (fp16, N=64 via zero-pad)
    mma_gemm_h16<1><<<dim3(1, NKROW / 128), 256, H16SMEM>>>(
        p_atd, p_w1p, p_b1p, nullptr, p_g1, DN, 64, DN / 32, 64);

    // 9) gate + weighted sum of output directions
    token_final<<<NTOK, 256>>>(p_g1, p_base, wp2, wp2b, p_idx, dirs, out);
}

// round 16
// speedup vs baseline: 1.1088x; 1.1088x over previous
#include <cuda_runtime.h>
#include <cuda_bf16.h>
#include <cuda_fp16.h>
#include <math.h>
#include <float.h>
#include <stdint.h>

// ---------------------------------------------------------------------------
// Problem constants
// ---------------------------------------------------------------------------
#define NTOK   4096
#define DMODEL 1024
#define DFF    4096
#define DN     128
#define NHEADS 8
#define HDIM   16
#define TOPK   32
#define NKROW  (NTOK * TOPK)   // 131072

// ---------------------------------------------------------------------------
// Scratch
// ---------------------------------------------------------------------------
__device__ float g_xn[NTOK * DMODEL];
__device__ float g_h[NTOK * DMODEL];
__device__ float g_scores[(size_t)NTOK * DFF];
__device__ int   g_idx[NTOK * TOPK];
__device__ float g_qkv[(size_t)NKROW * 3 * DN];
__device__ float g_ao[(size_t)NKROW * DN];
__device__ float g_atd[(size_t)NKROW * DN];
__device__ float g_g1[(size_t)NKROW * 64];
__device__ float g_base[NKROW];
__device__ float g_wp1pad[DN * DN];
__device__ float g_wp1bpad[DN];

// ---------------------------------------------------------------------------
// Helpers
// ---------------------------------------------------------------------------
__device__ __forceinline__ float gelu_f(float v) {
    return 0.5f * v * (1.0f + erff(v * 0.70710678118654752f));
}
__device__ __forceinline__ float warp_sum(float v) {
    #pragma unroll
    for (int o = 16; o > 0; o >>= 1) v += __shfl_xor_sync(0xffffffffu, v, o);
    return v;
}
__device__ __forceinline__ float warp_max(float v) {
    #pragma unroll
    for (int o = 16; o > 0; o >>= 1) v = fmaxf(v, __shfl_xor_sync(0xffffffffu, v, o));
    return v;
}
__device__ __forceinline__ float tf32_rna(float x) {
    float r;
    asm("cvt.rna.tf32.f32 %0, %1;" : "=f"(r) : "f"(x));
    return r;
}

// m16n8k8 tf32 mma
__device__ __forceinline__ void mma8(float* c, const uint32_t a[4], const uint32_t b[2]) {
    asm volatile(
        "mma.sync.aligned.m16n8k8.row.col.f32.tf32.tf32.f32 "
        "{%0,%1,%2,%3}, {%4,%5,%6,%7}, {%8,%9}, {%0,%1,%2,%3};"
        : "+f"(c[0]), "+f"(c[1]), "+f"(c[2]), "+f"(c[3])
        : "r"(a[0]), "r"(a[1]), "r"(a[2]), "r"(a[3]), "r"(b[0]), "r"(b[1]));
}
// m16n8k16 fp16 mma (fp32 accumulate)
__device__ __forceinline__ void mma16h(float* c, const uint32_t a[4], const uint32_t b[2]) {
    asm volatile(
        "mma.sync.aligned.m16n8k16.row.col.f32.f16.f16.f32 "
        "{%0,%1,%2,%3}, {%4,%5,%6,%7}, {%8,%9}, {%0,%1,%2,%3};"
        : "+f"(c[0]), "+f"(c[1]), "+f"(c[2]), "+f"(c[3])
        : "r"(a[0]), "r"(a[1]), "r"(a[2]), "r"(a[3]), "r"(b[0]), "r"(b[1]));
}

#define GS 36   // tf32 smem row stride in floats (32 data + 4 pad)

__device__ __forceinline__ void frag_a(uint32_t a[4], const float* S, int row, int kc, int lane) {
    int r = lane >> 2, c = lane & 3;
    a[0] = __float_as_uint(S[(row + r) * GS + kc + c]);
    a[1] = __float_as_uint(S[(row + r + 8) * GS + kc + c]);
    a[2] = __float_as_uint(S[(row + r) * GS + kc + c + 4]);
    a[3] = __float_as_uint(S[(row + r + 8) * GS + kc + c + 4]);
}
__device__ __forceinline__ void frag_b(uint32_t b[2], const float* S, int col, int kc, int lane) {
    int n = lane >> 2, c = lane & 3;
    b[0] = __float_as_uint(S[(col + n) * GS + kc + c]);
    b[1] = __float_as_uint(S[(col + n) * GS + kc + c + 4]);
}

// ---------------------------------------------------------------------------
// LayerNorm
// ---------------------------------------------------------------------------
__global__ void ln_kernel(const float* __restrict__ x,
                          const float* __restrict__ g,
                          const float* __restrict__ b,
                          float* __restrict__ xn) {
    __shared__ float red[16];
    __shared__ float s_mu, s_r;
    int n = blockIdx.x, tid = threadIdx.x, w = tid >> 5, lane = tid & 31;
    float4 v = ((const float4*)(x + (size_t)n * DMODEL))[tid];
    float s = v.x + v.y + v.z + v.w;
    float q = v.x * v.x + v.y * v.y + v.z * v.z + v.w * v.w;
    s = warp_sum(s); q = warp_sum(q);
    if (lane == 0) { red[w] = s; red[8 + w] = q; }
    __syncthreads();
    if (tid == 0) {
        float ts = 0.f, tq = 0.f;
        for (int i = 0; i < 8; i++) { ts += red[i]; tq += red[8 + i]; }
        float mu = ts * (1.0f / DMODEL);
        float var = tq * (1.0f / DMODEL) - mu * mu;
        s_mu = mu; s_r = rsqrtf(var + 1e-5f);
    }
    __syncthreads();
    float mu = s_mu, r = s_r;
    float4 gv = ((const float4*)g)[tid];
    float4 bv = ((const float4*)b)[tid];
    float4 o;
    o.x = (v.x - mu) * r * gv.x + bv.x;
    o.y = (v.y - mu) * r * gv.y + bv.y;
    o.z = (v.z - mu) * r * gv.z + bv.z;
    o.w = (v.w - mu) * r * gv.w + bv.w;
    ((float4*)(xn + (size_t)n * DMODEL))[tid] = o;
}

// ---------------------------------------------------------------------------
// 3xTF32 GEMM — WARP-SPECIALIZED: warps 0-3 load+split+stage (double-buffered),
// warps 4-11 run the proven R14 MMA loop untouched. 384 threads, CTA 128x128,
// 8 MMA warps of 64x32, K chunks of 32. One __syncthreads per chunk.
// ---------------------------------------------------------------------------
#define BUFSZ3 (4 * 128 * GS)
#define SMEM3DB (2 * BUFSZ3 * 4)

template <int ACT>
__global__ void __launch_bounds__(384, 1)
mma_gemm3(const float* __restrict__ A,
          const float* __restrict__ B,
          float* __restrict__ C,
          int K, int ldc, int kchunks) {
    extern __shared__ float sm[];

    int tid = threadIdx.x, lane = tid & 31, wid = tid >> 5;
    int m0 = blockIdx.y * 128, n0 = blockIdx.x * 128;

    if (wid < 4) {
        // ---------------- loader warps (128 threads) ----------------
        int rg = tid >> 3;          // 0..15
        int c4 = tid & 7;           // float4 column 0..7
        const float* Abase = A + (size_t)(m0 + rg) * K + c4 * 4;
        const float* Bbase = B + (size_t)(n0 + rg) * K + c4 * 4;

        auto stage_chunk = [&](int buf, int kbase) {
            float* Ah = sm + buf * BUFSZ3;
            float* Al = Ah + 128 * GS;
            float* Bh = Ah + 2 * 128 * GS;
            float* Bl = Bh + 128 * GS;
            #pragma unroll
            for (int i = 0; i < 8; i++) {
                int r = rg + 16 * i;
                float4 av = *(const float4*)(Abase + (size_t)(16 * i) * K + kbase);
                float4 bv = *(const float4*)(Bbase + (size_t)(16 * i) * K + kbase);
                float4 ah, bh, al, bl;
                ah.x = tf32_rna(av.x); ah.y = tf32_rna(av.y);
                ah.z = tf32_rna(av.z); ah.w = tf32_rna(av.w);
                bh.x = tf32_rna(bv.x); bh.y = tf32_rna(bv.y);
                bh.z = tf32_rna(bv.z); bh.w = tf32_rna(bv.w);
                al.x = tf32_rna(av.x - ah.x); al.y = tf32_rna(av.y - ah.y);
                al.z = tf32_rna(av.z - ah.z); al.w = tf32_rna(av.w - ah.w);
                bl.x = tf32_rna(bv.x - bh.x); bl.y = tf32_rna(bv.y - bh.y);
                bl.z = tf32_rna(bv.z - bh.z); bl.w = tf32_rna(bv.w - bh.w);
                *(float4*)&Ah[r * GS + c4 * 4] = ah;
                *(float4*)&Bh[r * GS + c4 * 4] = bh;
                *(float4*)&Al[r * GS + c4 * 4] = al;
                *(float4*)&Bl[r * GS + c4 * 4] = bl;
            }
        };

        stage_chunk(0, 0);
        __syncthreads();
        for (int ch = 0; ch < kchunks; ch++) {
            if (ch + 1 < kchunks) stage_chunk((ch + 1) & 1, (ch + 1) * 32);
            __syncthreads();
        }
        return;
    }

    // ---------------- MMA warps (256 threads, proven R14 loop) ----------------
    int mwid = wid - 4;
    int mw = (mwid >> 2) * 64, nw = (mwid & 3) * 32;

    float acc[4][4][4];
    #pragma unroll
    for (int mt = 0; mt < 4; mt++)
        #pragma unroll
        for (int nt = 0; nt < 4; nt++)
            #pragma unroll
            for (int e = 0; e < 4; e++) acc[mt][nt][e] = 0.f;

    __syncthreads();   // matches loaders' first barrier

    for (int ch = 0; ch < kchunks; ch++) {
        const float* Ah = sm + (ch & 1) * BUFSZ3;
        const float* Al = Ah + 128 * GS;
        const float* Bh = Ah + 2 * 128 * GS;
        const float* Bl = Bh + 128 * GS;

        #pragma unroll
        for (int kc = 0; kc < 32; kc += 8) {
            uint32_t af[4][4], bf[4][2];
            #pragma unroll
            for (int mt = 0; mt < 4; mt++) frag_a(af[mt], Ah, mw + mt * 16, kc, lane);
            #pragma unroll
            for (int nt = 0; nt < 4; nt++) frag_b(bf[nt], Bh, nw + nt * 8, kc, lane);
            #pragma unroll
            for (int mt = 0; mt < 4; mt++)
                #pragma unroll
                for (int nt = 0; nt < 4; nt++)
                    mma8(acc[mt][nt], af[mt], bf[nt]);

            uint32_t blf[4][2];
            #pragma unroll
            for (int nt = 0; nt < 4; nt++) frag_b(blf[nt], Bl, nw + nt * 8, kc, lane);
            #pragma unroll
            for (int mt = 0; mt < 4; mt++)
                #pragma unroll
                for (int nt = 0; nt < 4; nt++)
                    mma8(acc[mt][nt], af[mt], blf[nt]);

            uint32_t alf[4][4];
            #pragma unroll
            for (int mt = 0; mt < 4; mt++) frag_a(alf[mt], Al, mw + mt * 16, kc, lane);
            #pragma unroll
            for (int mt = 0; mt < 4; mt++)
                #pragma unroll
                for (int nt = 0; nt < 4; nt++)
                    mma8(acc[mt][nt], alf[mt], bf[nt]);
        }
        __syncthreads();
    }

    // epilogue (MMA warps only)
    int r = lane >> 2, c2 = (lane & 3) * 2;
    #pragma unroll
    for (int mt = 0; mt < 4; mt++) {
        #pragma unroll
        for (int nt = 0; nt < 4; nt++) {
            int row = m0 + mw + mt * 16 + r;
            int col = n0 + nw + nt * 8 + c2;
            float v0 = acc[mt][nt][0];
            float v1 = acc[mt][nt][1];
            float v2 = acc[mt][nt][2];
            float v3 = acc[mt][nt][3];
            if (ACT == 1) { v0 = gelu_f(v0); v1 = gelu_f(v1); v2 = gelu_f(v2); v3 = gelu_f(v3); }
            float2 lo; lo.x = v0; lo.y = v1;
            float2 hi; hi.x = v2; hi.y = v3;
            *(float2*)&C[(size_t)row * ldc + col] = lo;
            *(float2*)&C[(size_t)(row + 8) * ldc + col] = hi;
        }
    }
}

// ---------------------------------------------------------------------------
// FP16 1-pass GEMM (gate path only) — R14 proven single-buffered version.
// 256 thr, 8 warps, 64x32 warp tiles, CTA 128x128, K chunks of 32.
// ---------------------------------------------------------------------------
#define GSH 40
#define H16SMEM (2 * 128 * GSH * 2)

__device__ __forceinline__ void frag_a_h(uint32_t a[4], const __half* S, int row, int kc, int lane) {
    int r = lane >> 2, c = (lane & 3) * 2;
    a[0] = *(const uint32_t*)&S[(row + r) * GSH + kc + c];
    a[1] = *(const uint32_t*)&S[(row + r + 8) * GSH + kc + c];
    a[2] = *(const uint32_t*)&S[(row + r) * GSH + kc + c + 8];
    a[3] = *(const uint32_t*)&S[(row + r + 8) * GSH + kc + c + 8];
}
__device__ __forceinline__ void frag_b_h(uint32_t b[2], const __half* S, int col, int kc, int lane) {
    int n = lane >> 2, c = (lane & 3) * 2;
    b[0] = *(const uint32_t*)&S[(col + n) * GSH + kc + c];
    b[1] = *(const uint32_t*)&S[(col + n) * GSH + kc + c + 8];
}

template <int ACT>
__global__ void __launch_bounds__(256, 1)
mma_gemm_h16(const float* __restrict__ A,
             const float* __restrict__ B,
             const float* __restrict__ bias,
             const int* __restrict__ rowidx,
             float* __restrict__ C,
             int K, int ldc, int kchunks, int nvalid) {
    extern __shared__ __half smh[];
    __half* Ah = smh;
    __half* Bh = smh + 128 * GSH;

    int tid = threadIdx.x, lane = tid & 31, wid = tid >> 5;
    int m0 = blockIdx.y * 128, n0 = blockIdx.x * 128;
    int mw = (wid >> 2) * 64, nw = (wid & 3) * 32;

    int r0 = tid >> 3, c4 = tid & 7;
    const float* Ap[4];
    const float* Bp[4];
    #pragma unroll
    for (int i = 0; i < 4; i++) {
        int r = r0 + 32 * i;
        int ar = rowidx ? rowidx[m0 + r] : (m0 + r);
        Ap[i] = A + (size_t)ar * K + c4 * 4;
        Bp[i] = B + (size_t)(n0 + r) * K + c4 * 4;
    }

    float acc[4][4][4];
    #pragma unroll
    for (int mt = 0; mt < 4; mt++)
        #pragma unroll
        for (int nt = 0; nt < 4; nt++)
            #pragma unroll
            for (int e = 0; e < 4; e++) acc[mt][nt][e] = 0.f;

    float4 pa[4], pb[4];
    #pragma unroll
    for (int i = 0; i < 4; i++) { pa[i] = *(const float4*)Ap[i]; pb[i] = *(const float4*)Bp[i]; }

    for (int ch = 0; ch < kchunks; ch++) {
        #pragma unroll
        for (int i = 0; i < 4; i++) {
            int r = r0 + 32 * i;
            float4 av = pa[i], bv = pb[i];
            __half2 a01 = __floats2half2_rn(av.x, av.y);
            __half2 a23 = __floats2half2_rn(av.z, av.w);
            __half2 b01 = __floats2half2_rn(bv.x, bv.y);
            __half2 b23 = __floats2half2_rn(bv.z, bv.w);
            uint2 au; au.x = *(uint32_t*)&a01; au.y = *(uint32_t*)&a23;
            uint2 bu; bu.x = *(uint32_t*)&b01; bu.y = *(uint32_t*)&b23;
            *(uint2*)&Ah[r * GSH + c4 * 4] = au;
            *(uint2*)&Bh[r * GSH + c4 * 4] = bu;
        }
        __syncthreads();

        if (ch + 1 < kchunks) {
            int off = (ch + 1) * 32;
            #pragma unroll
            for (int i = 0; i < 4; i++) {
                pa[i] = *(const float4*)(Ap[i] + off);
                pb[i] = *(const float4*)(Bp[i] + off);
            }
        }

        #pragma unroll
        for (int kc = 0; kc < 32; kc += 16) {
            uint32_t af[4][4], bf[4][2];
            #pragma unroll
            for (int mt = 0; mt < 4; mt++) frag_a_h(af[mt], Ah, mw + mt * 16, kc, lane);
            #pragma unroll
            for (int nt = 0; nt < 4; nt++) frag_b_h(bf[nt], Bh, nw + nt * 8, kc, lane);
            #pragma unroll
            for (int mt = 0; mt < 4; mt++)
                #pragma unroll
                for (int nt = 0; nt < 4; nt++)
                    mma16h(acc[mt][nt], af[mt], bf[nt]);
        }
        __syncthreads();
    }

    int r = lane >> 2, c2 = (lane & 3) * 2;
    #pragma unroll
    for (int mt = 0; mt < 4; mt++) {
        #pragma unroll
        for (int nt = 0; nt < 4; nt++) {
            int row = m0 + mw + mt * 16 + r;
            int col = n0 + nw + nt * 8 + c2;
            if (col >= nvalid) continue;
            float b0 = bias ? bias[col] : 0.f;
            float b1 = bias ? bias[col + 1] : 0.f;
            float v0 = acc[mt][nt][0] + b0;
            float v1 = acc[mt][nt][1] + b1;
            float v2 = acc[mt][nt][2] + b0;
            float v3 = acc[mt][nt][3] + b1;
            if (ACT == 1) { v0 = gelu_f(v0); v1 = gelu_f(v1); v2 = gelu_f(v2); v3 = gelu_f(v3); }
            float2 lo; lo.x = v0; lo.y = v1;
            float2 hi; hi.x = v2; hi.y = v3;
            *(float2*)&C[(size_t)row * ldc + col] = lo;
            *(float2*)&C[(size_t)(row + 8) * ldc + col] = hi;
        }
    }
}

// ---------------------------------------------------------------------------
// Top-32 per row — cached per-thread argmax (proven 117-us version)
// ---------------------------------------------------------------------------
__global__ void topk_kernel(const float* __restrict__ scores,
                            int* __restrict__ idxout) {
    __shared__ float sv[DFF];
    __shared__ float swv[8];
    __shared__ int   swi[8];
    __shared__ int   sgi;
    int n = blockIdx.x, tid = threadIdx.x, w = tid >> 5, lane = tid & 31;
    const float4* s4 = (const float4*)(scores + (size_t)n * DFF);
    for (int i = tid; i < DFF / 4; i += 256)
        ((float4*)sv)[i] = s4[i];
    __syncthreads();

    float lmax = -FLT_MAX; int lidx = tid;
    #pragma unroll
    for (int t = 0; t < 16; t++) {
        int j = tid + 256 * t;
        float v = sv[j];
        if (v > lmax) { lmax = v; lidx = j; }
    }
    for (int r = 0; r < TOPK; r++) {
        float b = lmax; int bi = lidx;
        #pragma unroll
        for (int o = 16; o > 0; o >>= 1) {
            float ov = __shfl_down_sync(0xffffffffu, b, o);
            int   oi = __shfl_down_sync(0xffffffffu, bi, o);
            if (ov > b || (ov == b && oi < bi)) { b = ov; bi = oi; }
        }
        if (lane == 0) { swv[w] = b; swi[w] = bi; }
        __syncthreads();
        if (tid == 0) {
            float gb = swv[0]; int gi = swi[0];
            for (int q = 1; q < 8; q++)
                if (swv[q] > gb || (swv[q] == gb && swi[q] < gi)) { gb = swv[q]; gi = swi[q]; }
            idxout[n * TOPK + r] = gi;
            sgi = gi;
            sv[gi] = -FLT_MAX;
        }
        __syncthreads();
        int gi = sgi;
        if ((gi & 255) == tid) {
            lmax = -FLT_MAX; lidx = tid;
            #pragma unroll
            for (int t = 0; t < 16; t++) {
                int j = tid + 256 * t;
                float v = sv[j];
                if (v > lmax) { lmax = v; lidx = j; }
            }
        }
    }
}

// ---------------------------------------------------------------------------
// Pad wp1 [64,128] -> [128,128] (zeros) and wp1b [64] -> [128]
// ---------------------------------------------------------------------------
__global__ void pad_wp1_kernel(const float* __restrict__ wp1,
                               const float* __restrict__ wp1b,
                               float* __restrict__ wpad,
                               float* __restrict__ bpad) {
    int i = blockIdx.x * 256 + threadIdx.x;
    if (i < DN * DN) {
        int r = i >> 7;
        wpad[i] = (r < 64) ? wp1[i] : 0.f;
    }
    if (i < DN) bpad[i] = (i < 64) ? wp1b[i] : 0.f;
}

// ---------------------------------------------------------------------------
// token_attn: base gate + 8-head attention over k=32 neurons.
// ---------------------------------------------------------------------------
#define SQKV_STRIDE 388
#define ATTN_SMEM_FLOATS (12416 + 1024 + 1024 + 4096 + 32 + 32)

__global__ void token_attn(const float* __restrict__ x,
                           const float* __restrict__ pats,
                           const int* __restrict__ idx,
                           const float* __restrict__ qkv,
                           float* __restrict__ ao_out,
                           float* __restrict__ base_out) {
    extern __shared__ float smf[];
    float* sqkv  = smf;
    float* satt  = smf + 12416;
    float* sx    = smf + 13440;
    float* sao   = smf + 14464;
    float* sbase = smf + 18560;
    int*   skid  = (int*)(smf + 18592);

    int n = blockIdx.x, tid = threadIdx.x, w = tid >> 5, lane = tid & 31;

    if (tid < TOPK) skid[tid] = idx[n * TOPK + tid];
    ((float4*)sx)[tid] = ((const float4*)x)[(size_t)n * 256 + tid];
    __syncthreads();

    {
        const float* qn = qkv + (size_t)n * (TOPK * 3 * DN);
        for (int i = tid; i < TOPK * 3 * DN; i += 256) {
            int r = i / 384, c = i - r * 384;
            sqkv[r * SQKV_STRIDE + c] = qn[i];
        }
    }

    {
        const float4* xs = (const float4*)sx;
        #pragma unroll
        for (int r = 0; r < 4; r++) {
            int kk = w * 4 + r;
            const float4* p = (const float4*)(pats + (size_t)skid[kk] * DMODEL);
            float s = 0.f;
            #pragma unroll
            for (int j = 0; j < 8; j++) {
                int i = lane + 32 * j;
                float4 a = p[i], bq = xs[i];
                s += a.x * bq.x + a.y * bq.y + a.z * bq.z + a.w * bq.w;
            }
            s = warp_sum(s);
            if (lane == 0) sbase[kk] = gelu_f(s);
        }
    }
    __syncthreads();

    for (int h = 0; h < NHEADS; h++) {
        #pragma unroll
        for (int it = 0; it < 4; it++) {
            int e = tid + 256 * it;
            int qi = e >> 5, ki = e & 31;
            const float4* q4 = (const float4*)(sqkv + qi * SQKV_STRIDE + h * HDIM);
            const float4* k4 = (const float4*)(sqkv + ki * SQKV_STRIDE + DN + h * HDIM);
            float s = 0.f;
            #pragma unroll
            for (int j = 0; j < 4; j++) {
                float4 a = q4[j], b = k4[j];
                s += a.x * b.x + a.y * b.y + a.z * b.z + a.w * b.w;
            }
            satt[e] = s * 0.25f;
        }
        __syncthreads();
        #pragma unroll
        for (int r = 0; r < 4; r++) {
            int qi = w * 4 + r;
            float v = satt[qi * 32 + lane];
            float m = warp_max(v);
            float e2 = __expf(v - m);
            float s = warp_sum(e2);
            satt[qi * 32 + lane] = e2 / s;
        }
        __syncthreads();
        #pragma unroll
        for (int it = 0; it < 2; it++) {
            int e = tid + 256 * it;
            int qi = e >> 4, dc = e & 15;
            float s = 0.f;
            #pragma unroll
            for (int ki = 0; ki < 32; ki++)
                s = fmaf(satt[qi * 32 + ki], sqkv[ki * SQKV_STRIDE + 2 * DN + h * HDIM + dc], s);
            sao[qi * DN + h * HDIM + dc] = s;
        }
        __syncthreads();
    }

    {
        float* dst = ao_out + (size_t)n * (TOPK * DN);
        for (int i = tid; i < TOPK * DN / 4; i += 256)
            ((float4*)dst)[i] = ((const float4*)sao)[i];
        if (tid < TOPK) base_out[n * TOPK + tid] = sbase[tid];
    }
}

// ---------------------------------------------------------------------------
// token_final: gate = base * sigmoid(g1 . wp2 + b2); out = sum_k gate*dirs
// ---------------------------------------------------------------------------
__global__ void token_final(const float* __restrict__ g1,
                            const float* __restrict__ base,
                            const float* __restrict__ wp2,
                            const float* __restrict__ wp2b,
                            const int* __restrict__ idx,
                            const float* __restrict__ dirs,
                            float* __restrict__ out) {
    __shared__ float sgate[TOPK];
    __shared__ int   skid[TOPK];
    __shared__ float swp2[64];
    int n = blockIdx.x, tid = threadIdx.x, w = tid >> 5, lane = tid & 31;
    if (tid < 64) swp2[tid] = wp2[tid];
    if (tid < TOPK) skid[tid] = idx[n * TOPK + tid];
    __syncthreads();

    float b2 = wp2b[0];
    #pragma unroll
    for (int r = 0; r < 4; r++) {
        int k = w * 4 + r;
        const float* row = g1 + (size_t)(n * TOPK + k) * 64;
        float s = row[lane] * swp2[lane] + row[lane + 32] * swp2[lane + 32];
        s = warp_sum(s);
        if (lane == 0) {
            float sig = 1.0f / (1.0f + __expf(-(s + b2)));
            sgate[k] = base[n * TOPK + k] * sig;
        }
    }
    __syncthreads();

    float4 acc; acc.x = acc.y = acc.z = acc.w = 0.f;
    #pragma unroll 4
    for (int k = 0; k < TOPK; k++) {
        float g = sgate[k];
        const float4* dr = (const float4*)(dirs + (size_t)skid[k] * DMODEL);
        float4 v = dr[tid];
        acc.x = fmaf(g, v.x, acc.x);
        acc.y = fmaf(g, v.y, acc.y);
        acc.z = fmaf(g, v.z, acc.z);
        acc.w = fmaf(g, v.w, acc.w);
    }
    ((float4*)out)[(size_t)n * 256 + tid] = acc;
}

// ---------------------------------------------------------------------------
// Launch
// ---------------------------------------------------------------------------
extern "C" void kernel_launch(void* const* d_in, const int* in_sizes, int n_in,
                              void* d_out, int out_size) {
    const float* x    = (const float*)d_in[0];
    const float* pats = (const float*)d_in[1];
    const float* vecs = (const float*)d_in[2];
    const float* dirs = (const float*)d_in[3];
    const float* rw1  = (const float*)d_in[4];
    const float* rw2  = (const float*)d_in[5];
    const float* lng  = (const float*)d_in[6];
    const float* lnb  = (const float*)d_in[7];
    const float* inw  = (const float*)d_in[8];
    const float* inb  = (const float*)d_in[9];
    const float* outw = (const float*)d_in[10];
    const float* outb = (const float*)d_in[11];
    const float* wp1  = (const float*)d_in[12];
    const float* wp1b = (const float*)d_in[13];
    const float* wp2  = (const float*)d_in[14];
    const float* wp2b = (const float*)d_in[15];
    float* out = (float*)d_out;

    float *p_xn, *p_h, *p_scores, *p_qkv, *p_ao, *p_atd, *p_g1, *p_base, *p_w1p, *p_b1p;
    int *p_idx;
    cudaGetSymbolAddress((void**)&p_xn, g_xn);
    cudaGetSymbolAddress((void**)&p_h, g_h);
    cudaGetSymbolAddress((void**)&p_scores, g_scores);
    cudaGetSymbolAddress((void**)&p_idx, g_idx);
    cudaGetSymbolAddress((void**)&p_qkv, g_qkv);
    cudaGetSymbolAddress((void**)&p_ao, g_ao);
    cudaGetSymbolAddress((void**)&p_atd, g_atd);
    cudaGetSymbolAddress((void**)&p_g1, g_g1);
    cudaGetSymbolAddress((void**)&p_base, g_base);
    cudaGetSymbolAddress((void**)&p_w1p, g_wp1pad);
    cudaGetSymbolAddress((void**)&p_b1p, g_wp1bpad);

    static int attr_set = 0;
    if (!attr_set) {
        cudaFuncSetAttribute(token_attn,
                             cudaFuncAttributeMaxDynamicSharedMemorySize,
                             ATTN_SMEM_FLOATS * 4);
        cudaFuncSetAttribute(mma_gemm3<1>,
                             cudaFuncAttributeMaxDynamicSharedMemorySize, SMEM3DB);
        cudaFuncSetAttribute(mma_gemm3<0>,
                             cudaFuncAttributeMaxDynamicSharedMemorySize, SMEM3DB);
        cudaFuncSetAttribute(mma_gemm_h16<0>,
                             cudaFuncAttributeMaxDynamicSharedMemorySize, H16SMEM);
        cudaFuncSetAttribute(mma_gemm_h16<1>,
                             cudaFuncAttributeMaxDynamicSharedMemorySize, H16SMEM);
        attr_set = 1;
    }

    // 0) pad wp1 for the padded-N batched gemm
    pad_wp1_kernel<<<64, 256>>>(wp1, wp1b, p_w1p, p_b1p);

    // 1) LayerNorm
    ln_kernel<<<NTOK, 256>>>(x, lng, lnb, p_xn);

    // 2) h = gelu(xn @ rw1^T)   (3xTF32, warp-specialized)
    mma_gemm3<1><<<dim3(DMODEL / 128, NTOK / 128), 384, SMEM3DB>>>(
        p_xn, rw1, p_h, DMODEL, DMODEL, DMODEL / 32);

    // 3) scores = h @ rw2^T     (3xTF32, warp-specialized)
    mma_gemm3<0><<<dim3(DFF / 128, NTOK / 128), 384, SMEM3DB>>>(
        p_h, rw2, p_scores, DMODEL, DFF, DMODEL / 32);

    // 4) top-32 per token
    topk_kernel<<<NTOK, 256>>>(p_scores, p_idx);

    // 5) qkv = gather(neuron_vecs, idx) @ in_proj_w^T + b   (fp16, gate-safe)
    mma_gemm_h16<0><<<dim3((3 * DN) / 128, NKROW / 128), 256, H16SMEM>>>(
        vecs, inw, inb, p_idx, p_qkv, DN, 3 * DN, DN / 32, 3 * DN);

    // 6) per-token attention + base -> ao, base scratch
    token_attn<<<NTOK, 256, ATTN_SMEM_FLOATS * 4>>>(
        x, pats, p_idx, p_qkv, p_ao, p_base);

    // 7) attended = ao @ outw^T + outb   (fp16, batched over all (n,k) rows)
    mma_gemm_h16<0><<<dim3(1, NKROW / 128), 256, H16SMEM>>>(
        p_ao, outw, outb, nullptr, p_atd, DN, DN, DN / 32, DN);

    // 8) g1 = gelu(attended @ wp1^T + b1)  (fp16, N=64 via zero-pad)
    mma_gemm_h16<1><<<dim3(1, NKROW / 128), 256, H16SMEM>>>(
        p_atd, p_w1p, p_b1p, nullptr, p_g1, DN, 64, DN / 32, 64);

    // 9) gate + weighted sum of output directions
    token_final<<<NTOK, 256>>>(p_g1, p_base, wp2, wp2b, p_idx, dirs, out);
}